// round 14
// baseline (speedup 1.0000x reference)
#include <cuda_runtime.h>
#include <math.h>

#define N 384
#define D 128
#define TPB 512            // 16 warps; sort width 512 (128 +inf pads)
#define NWARP (TPB / 32)
#define FULL 0xFFFFFFFFu

#define TI 64              // precompute tile (64x64 outputs, K-chunks of 64)
#define TK 64

// Persistent accumulators. Zero at load; last block resets after finalizing so
// every invocation (correctness run + each graph replay) starts clean.
__device__ double   g_acc_trans = 0.0;
__device__ double   g_acc_hard  = 0.0;
__device__ unsigned g_done      = 0u;
// Pairwise scratch (overwritten every invocation before being read).
__device__ float    g_lmat[N * N];
__device__ float    g_emat[N * N];

// ---------------------------------------------------------------------------
// Kernel 1: all-pairs feature distance -> logits l and exp(e), diag e = 0.
// Exact same per-element fp32 accumulation order (k ascending) as before.
// ---------------------------------------------------------------------------
__global__ __launch_bounds__(256) void rnc_pre_kernel(const float* __restrict__ feat)
{
    __shared__ __align__(16) float As[TK][TI];   // 16 KB, [k][i]
    __shared__ __align__(16) float Bs[TK][TI];   // 16 KB, [k][j]

    const int bi = blockIdx.y, bj = blockIdx.x;
    const int t  = threadIdx.x;
    const int tx = t & 15, ty = t >> 4;

    float acc[4][4] = {};

    #pragma unroll 1
    for (int kc = 0; kc < D / TK; kc++) {
        // load both tiles transposed: thread t loads row r = t/4, k-quarter t%4
        const int r  = t >> 2;
        const int kq = (t & 3) * 16;
        #pragma unroll
        for (int u = 0; u < 4; u++) {
            int k0 = kq + u * 4;
            float4 va = *reinterpret_cast<const float4*>(
                feat + (bi * TI + r) * D + kc * TK + k0);
            As[k0+0][r] = va.x; As[k0+1][r] = va.y;
            As[k0+2][r] = va.z; As[k0+3][r] = va.w;
            float4 vb = *reinterpret_cast<const float4*>(
                feat + (bj * TI + r) * D + kc * TK + k0);
            Bs[k0+0][r] = vb.x; Bs[k0+1][r] = vb.y;
            Bs[k0+2][r] = vb.z; Bs[k0+3][r] = vb.w;
        }
        __syncthreads();

        #pragma unroll 8
        for (int k = 0; k < TK; k++) {
            float4 a4 = *reinterpret_cast<const float4*>(&As[k][ty * 4]);
            float4 b4 = *reinterpret_cast<const float4*>(&Bs[k][tx * 4]);
            float av[4] = {a4.x, a4.y, a4.z, a4.w};
            float bv[4] = {b4.x, b4.y, b4.z, b4.w};
            #pragma unroll
            for (int ii = 0; ii < 4; ii++)
                #pragma unroll
                for (int jj = 0; jj < 4; jj++) {
                    float d = av[ii] - bv[jj];
                    acc[ii][jj] = fmaf(d, d, acc[ii][jj]);
                }
        }
        __syncthreads();
    }

    // epilogue: l = -0.5*sqrt(sq) (zero-safe), e = exp(l), diag e = 0.
    // rowmax of logits is exactly 0 (l_ii = -0.5*sqrt(0), others <= 0).
    #pragma unroll
    for (int ii = 0; ii < 4; ii++) {
        int gi = bi * TI + ty * 4 + ii;
        int gj0 = bj * TI + tx * 4;
        float lv[4], ev[4];
        #pragma unroll
        for (int jj = 0; jj < 4; jj++) {
            float sq = acc[ii][jj];
            float l  = -((sq > 0.f) ? sqrtf(sq) : 0.f) * 0.5f;
            lv[jj] = l;
            ev[jj] = (gi == gj0 + jj) ? 0.f : expf(l);  // zero diag == offdiag
        }
        *reinterpret_cast<float4*>(&g_lmat[gi * N + gj0]) =
            make_float4(lv[0], lv[1], lv[2], lv[3]);
        *reinterpret_cast<float4*>(&g_emat[gi * N + gj0]) =
            make_float4(ev[0], ev[1], ev[2], ev[3]);
    }
}

// ---------------------------------------------------------------------------
// Kernel 2: per-row sort by td + suffix sums + masked den_hard + reduction.
// ---------------------------------------------------------------------------
__global__ __launch_bounds__(TPB) void rnc_main_kernel(
    const float* __restrict__ rgreen, // [N, 3]
    const float* __restrict__ rred,   // [N, 3]
    const float* __restrict__ trans,  // [N, 3]
    const int*   __restrict__ sym,    // [N, 1]
    float*       __restrict__ out)
{
    __shared__ __align__(16) float rd_sh[N];
    __shared__ __align__(16) float l_sh[N];
    __shared__ __align__(16) float e_sh[N];
    __shared__ __align__(16) float rd_p[N];     // rd permuted to sorted order
    __shared__ __align__(16) float e_p[N];      // e  permuted to sorted order
    __shared__ __align__(16) float den_h_sh[N];
    __shared__ __align__(16) unsigned long long key_sh[TPB];
    __shared__ float  wsum[NWARP];
    __shared__ double redt[NWARP];
    __shared__ double redh[NWARP];

    const int i    = blockIdx.x;
    const int tid  = threadIdx.x;
    const int lane = tid & 31;
    const int w    = tid >> 5;

    // ---- load this row's logits / exp weights (coalesced, precomputed) ----
    if (tid < N) {
        l_sh[tid] = g_lmat[i * N + tid];
        e_sh[tid] = g_emat[i * N + tid];
        den_h_sh[tid] = 0.f;
    }

    // ---- label diffs for j = tid (< N); build sort key ----
    unsigned long long key = 0xFFFFFFFFFFFFFFFFULL;   // +inf pad for tid >= N
    if (tid < N) {
        const int j = tid;
        float ti0 = trans[i*3+0], ti1 = trans[i*3+1], ti2 = trans[i*3+2]; // bcast
        float d0 = ti0 - trans[j*3+0];
        float d1 = ti1 - trans[j*3+1];
        float d2 = ti2 - trans[j*3+2];
        float a0 = fabsf(d0), a1 = fabsf(d1), a2 = fabsf(d2);
        float s = ((a0 < 1.f) ? 0.5f*d0*d0 : a0 - 0.5f)
                + ((a1 < 1.f) ? 0.5f*d1*d1 : a1 - 0.5f)
                + ((a2 < 1.f) ? 0.5f*d2*d2 : a2 - 0.5f);
        float tdv = s * (1.0f / 3.0f);

        const float EPSC = 1e-8f;
        float gi0 = rgreen[i*3+0], gi1 = rgreen[i*3+1], gi2 = rgreen[i*3+2];
        float ngi = fmaxf(sqrtf(gi0*gi0 + gi1*gi1 + gi2*gi2), EPSC);
        float gj0 = rgreen[j*3+0], gj1 = rgreen[j*3+1], gj2 = rgreen[j*3+2];
        float ngj = fmaxf(sqrtf(gj0*gj0 + gj1*gj1 + gj2*gj2), EPSC);
        float gd  = 1.0f - (gi0*gj0 + gi1*gj1 + gi2*gj2) / (ngi * ngj);

        float ri0 = rred[i*3+0], ri1 = rred[i*3+1], ri2 = rred[i*3+2];
        float nri = fmaxf(sqrtf(ri0*ri0 + ri1*ri1 + ri2*ri2), EPSC);
        float rj0 = rred[j*3+0], rj1 = rred[j*3+1], rj2 = rred[j*3+2];
        float nrj = fmaxf(sqrtf(rj0*rj0 + rj1*rj1 + rj2*rj2), EPSC);
        float rdd = 1.0f - (ri0*rj0 + ri1*rj1 + ri2*rj2) / (nri * nrj);

        bool psym = (sym[i] == 1) || (sym[j] == 1);
        rd_sh[j] = psym ? gd : gd + rdd;

        // key: td bits (non-negative float -> order-preserving) | index
        key = ((unsigned long long)__float_as_uint(tdv) << 32)
              | (unsigned long long)j;
    }

    // ---- hybrid bitonic sort, 512 register-held keys, ascending ----
    // jj < 32: intra-warp via shfl (no barrier). jj >= 32: via smem (2 barriers).
    for (int kk = 2; kk <= TPB; kk <<= 1) {
        for (int jj = kk >> 1; jj > 0; jj >>= 1) {
            unsigned long long other;
            if (jj >= 32) {
                __syncthreads();
                key_sh[tid] = key;
                __syncthreads();
                other = key_sh[tid ^ jj];
            } else {
                other = __shfl_xor_sync(FULL, key, jj);
            }
            bool up     = ((tid & kk) == 0);
            bool takeLo = (up == ((tid & jj) == 0));
            bool repl   = takeLo ? (other < key) : (other > key);
            key = repl ? other : key;
        }
    }
    __syncthreads();

    // ---- gather rd/e into sorted order; position p = tid (pads at p >= N) ----
    int   oj = -1;
    float e_own = 0.f;
    if (tid < N) {
        oj    = (int)(key & 0xFFFFFFFFULL);
        e_own = e_sh[oj];
        rd_p[tid] = rd_sh[oj];
        e_p[tid]  = e_own;
    }
    __syncthreads();

    // ---- suffix sum of e_p: den_trans[p] = sum_{q >= p} e_p[q] ----
    float den_t;
    {
        float pre = e_own;   // inclusive prefix within warp (pads contribute 0)
        #pragma unroll
        for (int o = 1; o < 32; o <<= 1) {
            float t = __shfl_up_sync(FULL, pre, o);
            if (lane >= o) pre += t;
        }
        float wtot = __shfl_sync(FULL, pre, 31);
        if (lane == 31) wsum[w] = pre;
        __syncthreads();
        float tail = 0.f;
        #pragma unroll
        for (int ww = 0; ww < NWARP; ww++) if (ww > w) tail += wsum[ww];
        den_t = tail + wtot - (pre - e_own);   // tail + in-warp inclusive suffix
    }

    // ---- den_hard[p] = sum_{q >= p, rd_p[q] >= rd_p[p]} e_p[q] ----
    // Warp w < 12 owns positions [32w, 32w+32), suffix chunks of 8 groups.
    // Static helpers: warps 12..15 take the back half of warps 0..3's ranges.
    {
        const float4* rd4 = reinterpret_cast<const float4*>(rd_p);
        const float4* e4  = reinterpret_cast<const float4*>(e_p);
        int wp, cbeg, cend;
        if (w < 12) {
            wp   = w;
            int nch = 12 - w;
            cbeg = 0;
            cend = (w < 4) ? (nch + 1) / 2 : nch;   // {6,6,5,5} if helped
        } else {
            wp   = w - 12;
            int nch = 12 - wp;                       // {12,11,10,9}
            cbeg = (nch + 1) / 2;                    // {6,6,5,5}
            cend = nch;
        }
        const int   p   = 32 * wp + lane;
        const float rdo = rd_p[p];
        float dh = 0.f, dh2 = 0.f;

        if (cbeg == 0) {
            // chunk 0: diagonal block, q >= p check needed
            #pragma unroll
            for (int g = 0; g < 8; g++) {
                int gg = 8 * wp + g;
                float4 rk = rd4[gg];
                float4 ek = e4[gg];
                int qb = 4 * gg;
                if (qb + 0 >= p && rdo <= rk.x) dh  += ek.x;
                if (qb + 1 >= p && rdo <= rk.y) dh2 += ek.y;
                if (qb + 2 >= p && rdo <= rk.z) dh  += ek.z;
                if (qb + 3 >= p && rdo <= rk.w) dh2 += ek.w;
            }
            cbeg = 1;
        }
        for (int c = cbeg; c < cend; c++) {
            int g0 = 8 * wp + 8 * c;
            #pragma unroll
            for (int g = 0; g < 8; g++) {
                int gg = g0 + g;
                float4 rk = rd4[gg];
                float4 ek = e4[gg];
                if (rdo <= rk.x) dh  += ek.x;
                if (rdo <= rk.y) dh2 += ek.y;
                if (rdo <= rk.z) dh  += ek.z;
                if (rdo <= rk.w) dh2 += ek.w;
            }
        }
        atomicAdd(&den_h_sh[p], dh + dh2);
    }
    __syncthreads();

    // ---- per-j log terms (skip diagonal j == i; pads contribute 0) ----
    double pos_t = 0.0, pos_h = 0.0;
    if (tid < N && oj != i) {
        float den_h = den_h_sh[tid];
        float l = l_sh[oj];
        pos_t = (double)(l - logf(den_t + 1e-7f));
        pos_h = (double)(l - logf(den_h + 1e-7f));
    }

    // ---- block reduction (double) ----
    #pragma unroll
    for (int o = 16; o; o >>= 1) {
        pos_t += __shfl_xor_sync(FULL, pos_t, o);
        pos_h += __shfl_xor_sync(FULL, pos_h, o);
    }
    if (lane == 0) { redt[w] = pos_t; redh[w] = pos_h; }
    __syncthreads();

    // ---- global accumulation + last-block finalize (self-resetting) ----
    if (tid == 0) {
        double at = 0.0, ah = 0.0;
        #pragma unroll
        for (int ww = 0; ww < NWARP; ww++) { at += redt[ww]; ah += redh[ww]; }
        atomicAdd(&g_acc_trans, at);
        atomicAdd(&g_acc_hard,  ah);
        __threadfence();
        unsigned ticket = atomicAdd(&g_done, 1u);
        if (ticket == (unsigned)(N - 1)) {
            double vt = atomicAdd(&g_acc_trans, 0.0);
            double vh = atomicAdd(&g_acc_hard,  0.0);
            const double denom = (double)N * (double)(N - 1);
            out[0] = (float)((-vh / denom) + 0.5 * (-vt / denom));
            g_acc_trans = 0.0;
            g_acc_hard  = 0.0;
            g_done      = 0u;
        }
    }
}

extern "C" void kernel_launch(void* const* d_in, const int* in_sizes, int n_in,
                              void* d_out, int out_size) {
    const float* feat   = (const float*)d_in[0];
    const float* rgreen = (const float*)d_in[1];
    const float* rred   = (const float*)d_in[2];
    const float* trans  = (const float*)d_in[3];
    const int*   sym    = (const int*)d_in[4];
    float* out = (float*)d_out;

    dim3 pgrid(N / TI, N / TI);
    rnc_pre_kernel<<<pgrid, 256>>>(feat);
    rnc_main_kernel<<<N, TPB>>>(rgreen, rred, trans, sym, out);
}

// round 15
// speedup vs baseline: 1.1511x; 1.1511x over previous
#include <cuda_runtime.h>
#include <math.h>

#define N 384
#define D 128
#define TPB 512            // 16 warps; sort width 512 (128 +inf pads)
#define NWARP (TPB / 32)
#define FULL 0xFFFFFFFFu

#define NPRE 144           // 12x12 grid of 32x32 tiles
#define PT 32              // pre tile size
#define PPAD 33            // smem row pad (bank-conflict-free scalar reads)

// Persistent accumulators. Zero at load; last block resets after finalizing so
// every invocation (correctness run + each graph replay) starts clean.
__device__ double   g_acc_trans = 0.0;
__device__ double   g_acc_hard  = 0.0;
__device__ unsigned g_done      = 0u;
__device__ unsigned g_pre_done  = 0u;
// Pairwise scratch (written each invocation before being read).
__device__ float    g_lmat[N * N];
__device__ float    g_emat[N * N];

// den_hard chunk schedule: 78 chunks (block b owns positions [32b,32b+32),
// chunk c covers groups [8(b+c), 8(b+c)+8)), flattened b-major. Warp w takes
// chunks [78w/16, 78(w+1)/16) -> at most 5 chunks per warp.
__constant__ unsigned char c_chb[78] = {
    0,0,0,0,0,0,0,0,0,0,0,0, 1,1,1,1,1,1,1,1,1,1,1, 2,2,2,2,2,2,2,2,2,2,
    3,3,3,3,3,3,3,3,3, 4,4,4,4,4,4,4,4, 5,5,5,5,5,5,5, 6,6,6,6,6,6,
    7,7,7,7,7, 8,8,8,8, 9,9,9, 10,10, 11};
__constant__ unsigned char c_chc[78] = {
    0,1,2,3,4,5,6,7,8,9,10,11, 0,1,2,3,4,5,6,7,8,9,10, 0,1,2,3,4,5,6,7,8,9,
    0,1,2,3,4,5,6,7,8, 0,1,2,3,4,5,6,7, 0,1,2,3,4,5,6, 0,1,2,3,4,5,
    0,1,2,3,4, 0,1,2,3, 0,1,2, 0,1, 0};

union SmemU {
    struct {
        float As[D][PPAD];   // [k][i], 16.9 KB
        float Bs[D][PPAD];   // [k][j]
    } pre;
    struct {
        float rd_sh[N];
        float l_sh[N];
        float e_sh[N];
        float rd_p[N];
        float e_p[N];
        float den_h[N];
        unsigned long long key[TPB];
        float  wsum[NWARP];
        double redt[NWARP];
        double redh[NWARP];
    } m;
};

__global__ __launch_bounds__(TPB) void rnc_fused_kernel(
    const float* __restrict__ feat,   // [N, D]
    const float* __restrict__ rgreen, // [N, 3]
    const float* __restrict__ rred,   // [N, 3]
    const float* __restrict__ trans,  // [N, 3]
    const int*   __restrict__ sym,    // [N, 1]
    float*       __restrict__ out)
{
    __shared__ SmemU s;

    const int bid  = blockIdx.x;
    const int i    = bid;             // row this block reduces
    const int tid  = threadIdx.x;
    const int lane = tid & 31;
    const int w    = tid >> 5;

    // =====================================================================
    // Phase A (blocks 0..143): produce one 32x32 tile of lmat/emat.
    // =====================================================================
    if (bid < NPRE) {
        const int tr = bid / 12, tc = bid % 12;
        // load both 32x128 tiles, k-major transposed (coalesced 512B/warp)
        #pragma unroll
        for (int u = 0; u < 2; u++) {
            int idx = tid + u * TPB;          // 0..1023 float4 slots
            int r   = idx >> 5;               // row in tile
            int c4  = idx & 31;               // float4 within row
            int k0  = c4 * 4;
            float4 va = *reinterpret_cast<const float4*>(feat + (tr * PT + r) * D + k0);
            s.pre.As[k0+0][r] = va.x; s.pre.As[k0+1][r] = va.y;
            s.pre.As[k0+2][r] = va.z; s.pre.As[k0+3][r] = va.w;
            float4 vb = *reinterpret_cast<const float4*>(feat + (tc * PT + r) * D + k0);
            s.pre.Bs[k0+0][r] = vb.x; s.pre.Bs[k0+1][r] = vb.y;
            s.pre.Bs[k0+2][r] = vb.z; s.pre.Bs[k0+3][r] = vb.w;
        }
        __syncthreads();

        if (tid < 256) {
            const int tx = tid & 15, ty = tid >> 4;   // 16x16, 2x2 micro-tile
            float a00 = 0.f, a01 = 0.f, a10 = 0.f, a11 = 0.f;
            #pragma unroll 8
            for (int k = 0; k < D; k++) {
                float x0 = s.pre.As[k][2*ty],   x1 = s.pre.As[k][2*ty+1];
                float y0 = s.pre.Bs[k][2*tx],   y1 = s.pre.Bs[k][2*tx+1];
                float d;
                d = x0 - y0; a00 = fmaf(d, d, a00);
                d = x0 - y1; a01 = fmaf(d, d, a01);
                d = x1 - y0; a10 = fmaf(d, d, a10);
                d = x1 - y1; a11 = fmaf(d, d, a11);
            }
            // epilogue: l = -0.5*sqrt (zero-safe); e = exp(l), diag e = 0.
            float accs[2][2] = {{a00, a01}, {a10, a11}};
            #pragma unroll
            for (int ii = 0; ii < 2; ii++) {
                int gi = tr * PT + 2 * ty + ii;
                #pragma unroll
                for (int jj = 0; jj < 2; jj++) {
                    int gj = tc * PT + 2 * tx + jj;
                    float sq = accs[ii][jj];
                    float l  = -((sq > 0.f) ? sqrtf(sq) : 0.f) * 0.5f;
                    g_lmat[gi * N + gj] = l;
                    g_emat[gi * N + gj] = (gi == gj) ? 0.f : expf(l);
                }
            }
        }
        __threadfence();
        __syncthreads();
        if (tid == 0) atomicAdd(&g_pre_done, 1u);
        __syncthreads();   // As/Bs dead from here; union reuse is safe
    }

    // =====================================================================
    // Phase B (all blocks): label diffs + sort keys (independent of feat).
    // =====================================================================
    unsigned long long key = 0xFFFFFFFFFFFFFFFFULL;   // +inf pad for tid >= N
    if (tid < N) {
        const int j = tid;
        float ti0 = trans[i*3+0], ti1 = trans[i*3+1], ti2 = trans[i*3+2]; // bcast
        float d0 = ti0 - trans[j*3+0];
        float d1 = ti1 - trans[j*3+1];
        float d2 = ti2 - trans[j*3+2];
        float a0 = fabsf(d0), a1 = fabsf(d1), a2 = fabsf(d2);
        float sm = ((a0 < 1.f) ? 0.5f*d0*d0 : a0 - 0.5f)
                 + ((a1 < 1.f) ? 0.5f*d1*d1 : a1 - 0.5f)
                 + ((a2 < 1.f) ? 0.5f*d2*d2 : a2 - 0.5f);
        float tdv = sm * (1.0f / 3.0f);

        const float EPSC = 1e-8f;
        float gi0 = rgreen[i*3+0], gi1 = rgreen[i*3+1], gi2 = rgreen[i*3+2];
        float ngi = fmaxf(sqrtf(gi0*gi0 + gi1*gi1 + gi2*gi2), EPSC);
        float gj0 = rgreen[j*3+0], gj1 = rgreen[j*3+1], gj2 = rgreen[j*3+2];
        float ngj = fmaxf(sqrtf(gj0*gj0 + gj1*gj1 + gj2*gj2), EPSC);
        float gd  = 1.0f - (gi0*gj0 + gi1*gj1 + gi2*gj2) / (ngi * ngj);

        float ri0 = rred[i*3+0], ri1 = rred[i*3+1], ri2 = rred[i*3+2];
        float nri = fmaxf(sqrtf(ri0*ri0 + ri1*ri1 + ri2*ri2), EPSC);
        float rj0 = rred[j*3+0], rj1 = rred[j*3+1], rj2 = rred[j*3+2];
        float nrj = fmaxf(sqrtf(rj0*rj0 + rj1*rj1 + rj2*rj2), EPSC);
        float rdd = 1.0f - (ri0*rj0 + ri1*rj1 + ri2*rj2) / (nri * nrj);

        bool psym = (sym[i] == 1) || (sym[j] == 1);
        s.m.rd_sh[j] = psym ? gd : gd + rdd;

        // key: td bits (non-negative float -> order-preserving) | index
        key = ((unsigned long long)__float_as_uint(tdv) << 32)
              | (unsigned long long)j;
    }

    // hybrid bitonic sort, 512 register-held keys, ascending:
    // jj < 32 via shfl (no barrier), jj >= 32 via smem (2 barriers).
    for (int kk = 2; kk <= TPB; kk <<= 1) {
        for (int jj = kk >> 1; jj > 0; jj >>= 1) {
            unsigned long long other;
            if (jj >= 32) {
                __syncthreads();
                s.m.key[tid] = key;
                __syncthreads();
                other = s.m.key[tid ^ jj];
            } else {
                other = __shfl_xor_sync(FULL, key, jj);
            }
            bool up     = ((tid & kk) == 0);
            bool takeLo = (up == ((tid & jj) == 0));
            bool repl   = takeLo ? (other < key) : (other > key);
            key = repl ? other : key;
        }
    }

    // =====================================================================
    // Phase C: wait for all lmat/emat tiles, then load this block's row.
    // =====================================================================
    if (tid == 0) {
        while (atomicAdd(&g_pre_done, 0u) < (unsigned)NPRE) __nanosleep(128);
        __threadfence();   // acquire: producers' STGs visible before row loads
    }
    __syncthreads();

    if (tid < N) {
        s.m.l_sh[tid]  = g_lmat[i * N + tid];
        s.m.e_sh[tid]  = g_emat[i * N + tid];
        s.m.den_h[tid] = 0.f;
    }
    __syncthreads();

    // gather rd/e into sorted order; position p = tid (pads at p >= N)
    int   oj = -1;
    float e_own = 0.f;
    if (tid < N) {
        oj    = (int)(key & 0xFFFFFFFFULL);
        e_own = s.m.e_sh[oj];
        s.m.rd_p[tid] = s.m.rd_sh[oj];
        s.m.e_p[tid]  = e_own;
    }
    __syncthreads();

    // suffix sum of e_p: den_trans[p] = sum_{q >= p} e_p[q]
    float den_t;
    {
        float pre = e_own;   // inclusive prefix within warp (pads contribute 0)
        #pragma unroll
        for (int o = 1; o < 32; o <<= 1) {
            float t = __shfl_up_sync(FULL, pre, o);
            if (lane >= o) pre += t;
        }
        float wtot = __shfl_sync(FULL, pre, 31);
        if (lane == 31) s.m.wsum[w] = pre;
        __syncthreads();
        float tail = 0.f;
        #pragma unroll
        for (int ww = 0; ww < NWARP; ww++) if (ww > w) tail += s.m.wsum[ww];
        den_t = tail + wtot - (pre - e_own);   // tail + in-warp inclusive suffix
    }

    // den_hard[p] = sum_{q >= p, rd_p[q] >= rd_p[p]} e_p[q]
    // Balanced: each warp runs <= 5 constant-table chunks.
    {
        const float4* rd4 = reinterpret_cast<const float4*>(s.m.rd_p);
        const float4* e4  = reinterpret_cast<const float4*>(s.m.e_p);
        const int beg = (w * 78) / NWARP;
        const int end = ((w + 1) * 78) / NWARP;
        for (int t = beg; t < end; t++) {
            const int b = c_chb[t];
            const int c = c_chc[t];
            const int p = 32 * b + lane;
            const float rdo = s.m.rd_p[p];
            const int g0 = 8 * (b + c);
            float dh = 0.f, dh2 = 0.f;
            if (c == 0) {
                #pragma unroll
                for (int g = 0; g < 8; g++) {
                    int gg = g0 + g;
                    float4 rk = rd4[gg];
                    float4 ek = e4[gg];
                    int qb = 4 * gg;
                    if (qb + 0 >= p && rdo <= rk.x) dh  += ek.x;
                    if (qb + 1 >= p && rdo <= rk.y) dh2 += ek.y;
                    if (qb + 2 >= p && rdo <= rk.z) dh  += ek.z;
                    if (qb + 3 >= p && rdo <= rk.w) dh2 += ek.w;
                }
            } else {
                #pragma unroll
                for (int g = 0; g < 8; g++) {
                    int gg = g0 + g;
                    float4 rk = rd4[gg];
                    float4 ek = e4[gg];
                    if (rdo <= rk.x) dh  += ek.x;
                    if (rdo <= rk.y) dh2 += ek.y;
                    if (rdo <= rk.z) dh  += ek.z;
                    if (rdo <= rk.w) dh2 += ek.w;
                }
            }
            atomicAdd(&s.m.den_h[p], dh + dh2);
        }
    }
    __syncthreads();

    // per-j log terms (skip diagonal j == i; pads contribute 0)
    double pos_t = 0.0, pos_h = 0.0;
    if (tid < N && oj != i) {
        float den_h = s.m.den_h[tid];
        float l = s.m.l_sh[oj];
        pos_t = (double)(l - logf(den_t + 1e-7f));
        pos_h = (double)(l - logf(den_h + 1e-7f));
    }

    // block reduction (double)
    #pragma unroll
    for (int o = 16; o; o >>= 1) {
        pos_t += __shfl_xor_sync(FULL, pos_t, o);
        pos_h += __shfl_xor_sync(FULL, pos_h, o);
    }
    if (lane == 0) { s.m.redt[w] = pos_t; s.m.redh[w] = pos_h; }
    __syncthreads();

    // global accumulation + last-block finalize (self-resetting)
    if (tid == 0) {
        double at = 0.0, ah = 0.0;
        #pragma unroll
        for (int ww = 0; ww < NWARP; ww++) { at += s.m.redt[ww]; ah += s.m.redh[ww]; }
        atomicAdd(&g_acc_trans, at);
        atomicAdd(&g_acc_hard,  ah);
        __threadfence();
        unsigned ticket = atomicAdd(&g_done, 1u);
        if (ticket == (unsigned)(N - 1)) {
            double vt = atomicAdd(&g_acc_trans, 0.0);
            double vh = atomicAdd(&g_acc_hard,  0.0);
            const double denom = (double)N * (double)(N - 1);
            out[0] = (float)((-vh / denom) + 0.5 * (-vt / denom));
            g_acc_trans = 0.0;
            g_acc_hard  = 0.0;
            g_done      = 0u;
            g_pre_done  = 0u;
        }
    }
}

extern "C" void kernel_launch(void* const* d_in, const int* in_sizes, int n_in,
                              void* d_out, int out_size) {
    const float* feat   = (const float*)d_in[0];
    const float* rgreen = (const float*)d_in[1];
    const float* rred   = (const float*)d_in[2];
    const float* trans  = (const float*)d_in[3];
    const int*   sym    = (const int*)d_in[4];
    float* out = (float*)d_out;

    rnc_fused_kernel<<<N, TPB>>>(feat, rgreen, rred, trans, sym, out);
}